// round 3
// baseline (speedup 1.0000x reference)
#include <cuda_runtime.h>
#include <cstdint>

// Problem constants
#define B_   32
#define HS_  512
#define C_   256
#define HW_  4096
#define A_   256
#define CHUNK 32              // pixels per block in the main pass
#define NCHUNK (HW_ / CHUNK)  // 128

// Scratch (allocation-free rule: __device__ globals)
__device__ float g_v[B_ * C_];             // v[b,c] = W_fm @ wh[b]
__device__ float g_m[B_ * NCHUNK];         // per-chunk local max
__device__ float g_s[B_ * NCHUNK];         // per-chunk exp-sum (local-max-relative)
__device__ float g_part[B_ * NCHUNK * C_]; // per-chunk partial context (4 MB)

// ---------------------------------------------------------------------------
// K1: wh[b] = h_dec[b] @ W_h + b_h ;  v[b,c] = sum_a W_fm[c,a] * wh[b,a]
// (b_fm dropped: per-batch constant in scores, cancels in softmax.)
// grid = B_, block = 256
// ---------------------------------------------------------------------------
__global__ __launch_bounds__(256) void prep_kernel(
    const float* __restrict__ h_dec,  // (B, HS)
    const float* __restrict__ W_h,    // (HS, A)
    const float* __restrict__ b_h,    // (A)
    const float* __restrict__ W_fm)   // (C, A)
{
    const int b = blockIdx.x;
    const int tid = threadIdx.x;

    __shared__ float sh_h[HS_];
    __shared__ float sh_wh[A_];

    sh_h[tid]       = h_dec[b * HS_ + tid];
    sh_h[tid + 256] = h_dec[b * HS_ + tid + 256];
    __syncthreads();

    float acc = b_h[tid];
    #pragma unroll 8
    for (int hs = 0; hs < HS_; ++hs)
        acc += sh_h[hs] * W_h[hs * A_ + tid];   // coalesced over tid
    sh_wh[tid] = acc;
    __syncthreads();

    const float* wrow = W_fm + (size_t)tid * A_;
    float vv = 0.f;
    #pragma unroll 8
    for (int a = 0; a < A_; ++a)
        vv += wrow[a] * sh_wh[a];
    g_v[b * C_ + tid] = vv;
}

// ---------------------------------------------------------------------------
// K2: main single-DRAM-pass kernel.
// grid = (NCHUNK, B), block = 256, STATIC smem only (~34.5 KB, no attribute).
// Stages fm[b, :, p0:p0+32] in shared, computes 32 scores, local softmax
// stats, and a partial context — fm read from DRAM exactly once.
// ---------------------------------------------------------------------------
__global__ __launch_bounds__(256) void pass_kernel(const float* __restrict__ fm)
{
    __shared__ float s_fm[C_ * CHUNK];   // [C_][CHUNK], 32 KB
    __shared__ float s_v[C_];
    __shared__ float s_red[256];
    __shared__ float s_w[CHUNK];
    __shared__ float s_bcast;

    const int b   = blockIdx.y;
    const int q   = blockIdx.x;
    const int p0  = q * CHUNK;
    const int tid = threadIdx.x;

    // stage v[b]
    s_v[tid] = g_v[b * C_ + tid];

    // stage fm chunk: C_*CHUNK floats = 2048 float4, 8 per thread (coalesced 128B rows)
    const float* fmb = fm + (size_t)b * C_ * HW_;
    {
        const int NV4 = C_ * CHUNK / 4;       // 2048
        #pragma unroll
        for (int i = tid; i < NV4; i += 256) {
            int c = i >> 3;                   // CHUNK/4 = 8 float4 per row
            int j = i & 7;
            float4 val = *((const float4*)(fmb + (size_t)c * HW_ + p0) + j);
            ((float4*)s_fm)[c * 8 + j] = val;
        }
    }
    __syncthreads();

    // Phase A: scores. 8 threads per pixel, each covers a 32-channel slice.
    {
        const int p  = tid & 31;
        const int g  = tid >> 5;              // 0..7
        const int c0 = g * 32;
        float acc = 0.f;
        #pragma unroll 8
        for (int c = c0; c < c0 + 32; ++c)
            acc = fmaf(s_fm[c * CHUNK + p], s_v[c], acc);
        s_red[tid] = acc;
    }
    __syncthreads();

    // warp 0: fold 8 partials per pixel, max, exp, sum
    if (tid < 32) {
        float sc = s_red[tid];
        #pragma unroll
        for (int g = 1; g < 8; ++g) sc += s_red[tid + 32 * g];

        float m = sc;
        #pragma unroll
        for (int o = 16; o > 0; o >>= 1)
            m = fmaxf(m, __shfl_xor_sync(0xffffffffu, m, o));

        float w = __expf(sc - m);
        s_w[tid] = w;

        float s = w;
        #pragma unroll
        for (int o = 16; o > 0; o >>= 1)
            s += __shfl_xor_sync(0xffffffffu, s, o);

        if (tid == 0) {
            g_m[b * NCHUNK + q] = m;
            g_s[b * NCHUNK + q] = s;
            s_bcast = m;   // (unused downstream; kept for clarity)
        }
    }
    __syncthreads();

    // Phase B: partial context. One warp per channel row; lanes over 32 pixels.
    {
        const int warp = tid >> 5;
        const int lane = tid & 31;
        float* part = g_part + ((size_t)(b * NCHUNK + q)) * C_;
        for (int c = warp; c < C_; c += 8) {
            float a = s_fm[c * CHUNK + lane] * s_w[lane];
            #pragma unroll
            for (int o = 16; o > 0; o >>= 1)
                a += __shfl_xor_sync(0xffffffffu, a, o);
            if (lane == 0) part[c] = a;
        }
    }
}

// ---------------------------------------------------------------------------
// K3: combine chunk partials exactly (max-rescaled).
// grid = B, block = 256
// ---------------------------------------------------------------------------
__global__ __launch_bounds__(256) void combine_kernel(float* __restrict__ out)
{
    const int b = blockIdx.x;
    const int tid = threadIdx.x;

    __shared__ float s_coef[NCHUNK];
    __shared__ float s_bcastM;
    __shared__ float s_bcastZ;

    // global max over 128 chunk maxima
    if (tid < 32) {
        const float* mb = g_m + b * NCHUNK;
        float m = fmaxf(fmaxf(mb[tid], mb[tid + 32]),
                        fmaxf(mb[tid + 64], mb[tid + 96]));
        #pragma unroll
        for (int o = 16; o > 0; o >>= 1)
            m = fmaxf(m, __shfl_xor_sync(0xffffffffu, m, o));
        if (tid == 0) s_bcastM = m;
    }
    __syncthreads();
    const float M = s_bcastM;

    if (tid < NCHUNK)
        s_coef[tid] = __expf(g_m[b * NCHUNK + tid] - M);
    __syncthreads();

    if (tid < 32) {
        const float* sb = g_s + b * NCHUNK;
        float z = sb[tid]      * s_coef[tid]
                + sb[tid + 32] * s_coef[tid + 32]
                + sb[tid + 64] * s_coef[tid + 64]
                + sb[tid + 96] * s_coef[tid + 96];
        #pragma unroll
        for (int o = 16; o > 0; o >>= 1)
            z += __shfl_xor_sync(0xffffffffu, z, o);
        if (tid == 0) s_bcastZ = z;
    }
    __syncthreads();
    const float invZ = 1.0f / s_bcastZ;

    // ctx[b,c] = sum_q part[b,q,c] * coef[q] / Z
    float acc = 0.f;
    const float* base = g_part + (size_t)b * NCHUNK * C_;
    #pragma unroll 8
    for (int qq = 0; qq < NCHUNK; ++qq)
        acc = fmaf(base[qq * C_ + tid], s_coef[qq], acc);
    out[b * C_ + tid] = acc * invZ;
}

// ---------------------------------------------------------------------------
// Launch. Input order (metadata): h_dec, fm, W_fm, b_fm(unused), W_h, b_h
// Plain kernel launches only — nothing else.
// ---------------------------------------------------------------------------
extern "C" void kernel_launch(void* const* d_in, const int* in_sizes, int n_in,
                              void* d_out, int out_size)
{
    const float* h_dec = (const float*)d_in[0];
    const float* fm    = (const float*)d_in[1];
    const float* W_fm  = (const float*)d_in[2];
    // d_in[3] = b_fm — cancels in softmax, unused
    const float* W_h   = (const float*)d_in[4];
    const float* b_h   = (const float*)d_in[5];
    float* out = (float*)d_out;

    prep_kernel<<<B_, 256>>>(h_dec, W_h, b_h, W_fm);
    pass_kernel<<<dim3(NCHUNK, B_), 256>>>(fm);
    combine_kernel<<<B_, 256>>>(out);
}

// round 4
// speedup vs baseline: 2.2724x; 2.2724x over previous
#include <cuda_runtime.h>
#include <cstdint>

// Problem constants
#define B_    32
#define HS_   512
#define C_    256
#define HW_   4096
#define A_    256
#define CHUNK 32               // pixels per block in the main pass
#define NCHUNK (HW_ / CHUNK)   // 128
#define KSPLIT 8               // split-K factor for wh

// Scratch (allocation-free rule: __device__ globals)
__device__ float g_whp[B_ * KSPLIT * A_];   // split-K partials of wh
__device__ float g_v[B_ * C_];              // v[b,c] = W_fm @ wh[b]
__device__ float g_m[B_ * NCHUNK];          // per-chunk local max
__device__ float g_s[B_ * NCHUNK];          // per-chunk exp-sum
__device__ float g_part[B_ * NCHUNK * C_];  // per-chunk partial context (4 MB)

// ---------------------------------------------------------------------------
// K1a: split-K partial of wh[b] = h_dec[b] @ W_h.
// grid = (B_, KSPLIT) = 256 blocks, block = 256 (one thread per output a).
// Each block covers 64 hs rows. Deterministic (fixed split order, no atomics).
// ---------------------------------------------------------------------------
__global__ __launch_bounds__(256) void prep_a_kernel(
    const float* __restrict__ h_dec,  // (B, HS)
    const float* __restrict__ W_h)    // (HS, A)
{
    const int b   = blockIdx.x;
    const int s   = blockIdx.y;
    const int tid = threadIdx.x;
    const int hs0 = s * (HS_ / KSPLIT);     // 64 rows per split

    __shared__ float sh[HS_ / KSPLIT];
    if (tid < HS_ / KSPLIT)
        sh[tid] = h_dec[b * HS_ + hs0 + tid];
    __syncthreads();

    float acc = 0.f;
    #pragma unroll 8
    for (int hs = 0; hs < HS_ / KSPLIT; ++hs)
        acc = fmaf(sh[hs], W_h[(size_t)(hs0 + hs) * A_ + tid], acc);  // coalesced
    g_whp[(b * KSPLIT + s) * A_ + tid] = acc;
}

// ---------------------------------------------------------------------------
// K1b: fold split-K partials + b_h -> wh (smem); then v[b,c] = W_fm[c,:]·wh.
// grid = B_, block = 256. b_fm dropped (cancels in softmax).
// ---------------------------------------------------------------------------
__global__ __launch_bounds__(256) void prep_b_kernel(
    const float* __restrict__ b_h,    // (A)
    const float* __restrict__ W_fm)   // (C, A)
{
    const int b   = blockIdx.x;
    const int tid = threadIdx.x;

    __shared__ float wh[A_];

    float acc = b_h[tid];
    #pragma unroll
    for (int s = 0; s < KSPLIT; ++s)
        acc += g_whp[(b * KSPLIT + s) * A_ + tid];   // coalesced
    wh[tid] = acc;
    __syncthreads();

    // v[b,c], c = tid; per-thread contiguous float4 over W_fm row
    const float4* wrow = (const float4*)(W_fm + (size_t)tid * A_);
    float vv = 0.f;
    #pragma unroll 8
    for (int a4 = 0; a4 < A_ / 4; ++a4) {
        float4 w4 = wrow[a4];
        vv = fmaf(w4.x, wh[a4 * 4 + 0],
             fmaf(w4.y, wh[a4 * 4 + 1],
             fmaf(w4.z, wh[a4 * 4 + 2],
             fmaf(w4.w, wh[a4 * 4 + 3], vv))));
    }
    g_v[b * C_ + tid] = vv;
}

// ---------------------------------------------------------------------------
// K2: main single-DRAM-pass kernel, register-resident fm.
// grid = (NCHUNK, B), block = 256.
// Thread owns pixel-quad j = tid&7 (4 pixels) x 8 channels (g + 32k).
// Loads are 8 independent float4 (coalesced 128B/warp-row); scores partials
// computed inline; context partials recomputed from the same registers.
// Padded smem (33, 9 strides coprime with 32) -> conflict-free reductions.
// ---------------------------------------------------------------------------
__global__ __launch_bounds__(256) void pass_kernel(const float* __restrict__ fm)
{
    __shared__ float s_red[CHUNK * 33];   // [pixel][group] padded
    __shared__ float s_part[C_ * 9];      // [channel][quad] padded
    __shared__ float s_w[CHUNK];

    const int b     = blockIdx.y;
    const int q     = blockIdx.x;
    const int p0    = q * CHUNK;
    const int tid   = threadIdx.x;
    const int j     = tid & 7;            // quad (4 pixels)
    const int g     = tid >> 3;           // channel group 0..31
    const int pbase = j * 4;

    // preload v for my 8 channels (independent loads)
    float vreg[8];
    #pragma unroll
    for (int k = 0; k < 8; ++k)
        vreg[k] = g_v[b * C_ + g + 32 * k];

    // load fm: 8 independent float4 per thread (front-batched MLP)
    const float* fmb = fm + (size_t)b * C_ * HW_ + p0;
    float4 val[8];
    #pragma unroll
    for (int k = 0; k < 8; ++k)
        val[k] = *((const float4*)(fmb + (size_t)(g + 32 * k) * HW_) + j);

    // inline score partials for my 4 pixels over my 8 channels
    float sc0 = 0.f, sc1 = 0.f, sc2 = 0.f, sc3 = 0.f;
    #pragma unroll
    for (int k = 0; k < 8; ++k) {
        sc0 = fmaf(val[k].x, vreg[k], sc0);
        sc1 = fmaf(val[k].y, vreg[k], sc1);
        sc2 = fmaf(val[k].z, vreg[k], sc2);
        sc3 = fmaf(val[k].w, vreg[k], sc3);
    }
    s_red[(pbase + 0) * 33 + g] = sc0;
    s_red[(pbase + 1) * 33 + g] = sc1;
    s_red[(pbase + 2) * 33 + g] = sc2;
    s_red[(pbase + 3) * 33 + g] = sc3;
    __syncthreads();

    // warp 0: fold 32 group-partials per pixel, then max / exp / sum
    if (tid < 32) {
        float sc = 0.f;
        #pragma unroll
        for (int gg = 0; gg < 32; ++gg)
            sc += s_red[tid * 33 + gg];           // banks (tid+gg)%32: clean

        float m = sc;
        #pragma unroll
        for (int o = 16; o > 0; o >>= 1)
            m = fmaxf(m, __shfl_xor_sync(0xffffffffu, m, o));

        float w = __expf(sc - m);
        s_w[tid] = w;

        float ssum = w;
        #pragma unroll
        for (int o = 16; o > 0; o >>= 1)
            ssum += __shfl_xor_sync(0xffffffffu, ssum, o);

        if (tid == 0) {
            g_m[b * NCHUNK + q] = m;
            g_s[b * NCHUNK + q] = ssum;
        }
    }
    __syncthreads();

    // context partials straight from registers
    const float w0 = s_w[pbase + 0];
    const float w1 = s_w[pbase + 1];
    const float w2 = s_w[pbase + 2];
    const float w3 = s_w[pbase + 3];
    #pragma unroll
    for (int k = 0; k < 8; ++k) {
        float a = fmaf(val[k].x, w0,
                  fmaf(val[k].y, w1,
                  fmaf(val[k].z, w2, val[k].w * w3)));
        s_part[(g + 32 * k) * 9 + j] = a;
    }
    __syncthreads();

    // fold 8 quads per channel, coalesced store
    float acc = 0.f;
    #pragma unroll
    for (int jj = 0; jj < 8; ++jj)
        acc += s_part[tid * 9 + jj];              // banks (9*tid+jj)%32: clean
    g_part[((size_t)(b * NCHUNK + q)) * C_ + tid] = acc;
}

// ---------------------------------------------------------------------------
// K3: combine chunk partials exactly (max-rescaled).
// grid = B, block = 256
// ---------------------------------------------------------------------------
__global__ __launch_bounds__(256) void combine_kernel(float* __restrict__ out)
{
    const int b   = blockIdx.x;
    const int tid = threadIdx.x;

    __shared__ float s_coef[NCHUNK];
    __shared__ float s_bcastM;
    __shared__ float s_bcastZ;

    if (tid < 32) {
        const float* mb = g_m + b * NCHUNK;
        float m = fmaxf(fmaxf(mb[tid], mb[tid + 32]),
                        fmaxf(mb[tid + 64], mb[tid + 96]));
        #pragma unroll
        for (int o = 16; o > 0; o >>= 1)
            m = fmaxf(m, __shfl_xor_sync(0xffffffffu, m, o));
        if (tid == 0) s_bcastM = m;
    }
    __syncthreads();
    const float M = s_bcastM;

    if (tid < NCHUNK)
        s_coef[tid] = __expf(g_m[b * NCHUNK + tid] - M);
    __syncthreads();

    if (tid < 32) {
        const float* sb = g_s + b * NCHUNK;
        float z = sb[tid]      * s_coef[tid]
                + sb[tid + 32] * s_coef[tid + 32]
                + sb[tid + 64] * s_coef[tid + 64]
                + sb[tid + 96] * s_coef[tid + 96];
        #pragma unroll
        for (int o = 16; o > 0; o >>= 1)
            z += __shfl_xor_sync(0xffffffffu, z, o);
        if (tid == 0) s_bcastZ = z;
    }
    __syncthreads();
    const float invZ = 1.0f / s_bcastZ;

    float acc = 0.f;
    const float* base = g_part + (size_t)b * NCHUNK * C_;
    #pragma unroll 8
    for (int qq = 0; qq < NCHUNK; ++qq)
        acc = fmaf(base[qq * C_ + tid], s_coef[qq], acc);   // coalesced
    out[b * C_ + tid] = acc * invZ;
}

// ---------------------------------------------------------------------------
// Launch. Input order (metadata): h_dec, fm, W_fm, b_fm(unused), W_h, b_h
// ---------------------------------------------------------------------------
extern "C" void kernel_launch(void* const* d_in, const int* in_sizes, int n_in,
                              void* d_out, int out_size)
{
    const float* h_dec = (const float*)d_in[0];
    const float* fm    = (const float*)d_in[1];
    const float* W_fm  = (const float*)d_in[2];
    // d_in[3] = b_fm — cancels in softmax, unused
    const float* W_h   = (const float*)d_in[4];
    const float* b_h   = (const float*)d_in[5];
    float* out = (float*)d_out;

    prep_a_kernel<<<dim3(B_, KSPLIT), 256>>>(h_dec, W_h);
    prep_b_kernel<<<B_, 256>>>(b_h, W_fm);
    pass_kernel<<<dim3(NCHUNK, B_), 256>>>(fm);
    combine_kernel<<<B_, 256>>>(out);
}

// round 6
// speedup vs baseline: 2.9574x; 1.3015x over previous
#include <cuda_runtime.h>
#include <cstdint>

// Problem constants
#define B_    32
#define HS_   512
#define C_    256
#define HW_   4096
#define A_    256
#define CHUNK 32               // pixels per block in the main pass
#define NCHUNK (HW_ / CHUNK)   // 128
#define KSPLIT 8               // split-K factor for wh
#define QSPLIT 8               // split factor for the combine reduction
#define QPER  (NCHUNK / QSPLIT) // 16 chunks per combine block

// Scratch (allocation-free rule: __device__ globals)
__device__ float g_whp[B_ * KSPLIT * A_];    // split-K partials of wh
__device__ float g_v[B_ * C_];               // v[b,c] = W_fm @ wh[b]
__device__ float g_m[B_ * NCHUNK];           // per-chunk local max
__device__ float g_s[B_ * NCHUNK];           // per-chunk exp-sum
__device__ float g_part[B_ * NCHUNK * C_];   // per-chunk partial context (4 MB)
__device__ float g_part2[B_ * QSPLIT * C_];  // combine split partials (256 KB)

// ---------------------------------------------------------------------------
// K1a: split-K partial of wh[b] = h_dec[b] @ W_h.
// grid = (B_, KSPLIT) = 256 blocks, block = 256 (one thread per output a).
// ---------------------------------------------------------------------------
__global__ __launch_bounds__(256) void prep_a_kernel(
    const float* __restrict__ h_dec,  // (B, HS)
    const float* __restrict__ W_h)    // (HS, A)
{
    const int b   = blockIdx.x;
    const int s   = blockIdx.y;
    const int tid = threadIdx.x;
    const int hs0 = s * (HS_ / KSPLIT);     // 64 rows per split

    __shared__ float sh[HS_ / KSPLIT];
    if (tid < HS_ / KSPLIT)
        sh[tid] = h_dec[b * HS_ + hs0 + tid];
    __syncthreads();

    float acc = 0.f;
    #pragma unroll 8
    for (int hs = 0; hs < HS_ / KSPLIT; ++hs)
        acc = fmaf(sh[hs], W_h[(size_t)(hs0 + hs) * A_ + tid], acc);  // coalesced
    g_whp[(b * KSPLIT + s) * A_ + tid] = acc;
}

// ---------------------------------------------------------------------------
// K1b: fold split-K partials + b_h -> wh (smem); then v[b,c] = W_fm[c,:]·wh.
// grid = B_, block = 256. b_fm dropped (cancels in softmax).
// ---------------------------------------------------------------------------
__global__ __launch_bounds__(256) void prep_b_kernel(
    const float* __restrict__ b_h,    // (A)
    const float* __restrict__ W_fm)   // (C, A)
{
    const int b   = blockIdx.x;
    const int tid = threadIdx.x;

    __shared__ float wh[A_];

    float acc = b_h[tid];
    #pragma unroll
    for (int s = 0; s < KSPLIT; ++s)
        acc += g_whp[(b * KSPLIT + s) * A_ + tid];   // coalesced
    wh[tid] = acc;
    __syncthreads();

    const float4* wrow = (const float4*)(W_fm + (size_t)tid * A_);
    float vv = 0.f;
    #pragma unroll 8
    for (int a4 = 0; a4 < A_ / 4; ++a4) {
        float4 w4 = wrow[a4];
        vv = fmaf(w4.x, wh[a4 * 4 + 0],
             fmaf(w4.y, wh[a4 * 4 + 1],
             fmaf(w4.z, wh[a4 * 4 + 2],
             fmaf(w4.w, wh[a4 * 4 + 3], vv))));
    }
    g_v[b * C_ + tid] = vv;
}

// ---------------------------------------------------------------------------
// K2: main single-DRAM-pass kernel, register-resident fm.
// grid = (NCHUNK, B), block = 256.
// ---------------------------------------------------------------------------
__global__ __launch_bounds__(256) void pass_kernel(const float* __restrict__ fm)
{
    __shared__ float s_red[CHUNK * 33];   // [pixel][group] padded
    __shared__ float s_part[C_ * 9];      // [channel][quad] padded
    __shared__ float s_w[CHUNK];

    const int b     = blockIdx.y;
    const int q     = blockIdx.x;
    const int p0    = q * CHUNK;
    const int tid   = threadIdx.x;
    const int j     = tid & 7;            // quad (4 pixels)
    const int g     = tid >> 3;           // channel group 0..31
    const int pbase = j * 4;

    // preload v for my 8 channels
    float vreg[8];
    #pragma unroll
    for (int k = 0; k < 8; ++k)
        vreg[k] = g_v[b * C_ + g + 32 * k];

    // load fm: 8 independent float4, streaming (read-once)
    const float* fmb = fm + (size_t)b * C_ * HW_ + p0;
    float4 val[8];
    #pragma unroll
    for (int k = 0; k < 8; ++k)
        val[k] = __ldcs((const float4*)(fmb + (size_t)(g + 32 * k) * HW_) + j);

    // inline score partials for my 4 pixels over my 8 channels
    float sc0 = 0.f, sc1 = 0.f, sc2 = 0.f, sc3 = 0.f;
    #pragma unroll
    for (int k = 0; k < 8; ++k) {
        sc0 = fmaf(val[k].x, vreg[k], sc0);
        sc1 = fmaf(val[k].y, vreg[k], sc1);
        sc2 = fmaf(val[k].z, vreg[k], sc2);
        sc3 = fmaf(val[k].w, vreg[k], sc3);
    }
    s_red[(pbase + 0) * 33 + g] = sc0;
    s_red[(pbase + 1) * 33 + g] = sc1;
    s_red[(pbase + 2) * 33 + g] = sc2;
    s_red[(pbase + 3) * 33 + g] = sc3;
    __syncthreads();

    // warp 0: fold 32 group-partials per pixel, then max / exp / sum
    if (tid < 32) {
        float sc = 0.f;
        #pragma unroll
        for (int gg = 0; gg < 32; ++gg)
            sc += s_red[tid * 33 + gg];

        float m = sc;
        #pragma unroll
        for (int o = 16; o > 0; o >>= 1)
            m = fmaxf(m, __shfl_xor_sync(0xffffffffu, m, o));

        float w = __expf(sc - m);
        s_w[tid] = w;

        float ssum = w;
        #pragma unroll
        for (int o = 16; o > 0; o >>= 1)
            ssum += __shfl_xor_sync(0xffffffffu, ssum, o);

        if (tid == 0) {
            g_m[b * NCHUNK + q] = m;
            g_s[b * NCHUNK + q] = ssum;
        }
    }
    __syncthreads();

    // context partials straight from registers
    const float w0 = s_w[pbase + 0];
    const float w1 = s_w[pbase + 1];
    const float w2 = s_w[pbase + 2];
    const float w3 = s_w[pbase + 3];
    #pragma unroll
    for (int k = 0; k < 8; ++k) {
        float a = fmaf(val[k].x, w0,
                  fmaf(val[k].y, w1,
                  fmaf(val[k].z, w2, val[k].w * w3)));
        s_part[(g + 32 * k) * 9 + j] = a;
    }
    __syncthreads();

    // fold 8 quads per channel, coalesced store
    float acc = 0.f;
    #pragma unroll
    for (int jj = 0; jj < 8; ++jj)
        acc += s_part[tid * 9 + jj];
    g_part[((size_t)(b * NCHUNK + q)) * C_ + tid] = acc;
}

// ---------------------------------------------------------------------------
// K3a: split combine. grid = (B_, QSPLIT) = 256 blocks, block = 256.
// Each block recomputes M, Z from the tiny g_m/g_s arrays (L2-resident),
// then reduces its 16 chunks with coef*invZ folded in. Deterministic.
// ---------------------------------------------------------------------------
__global__ __launch_bounds__(256) void combine_split_kernel()
{
    const int b   = blockIdx.x;
    const int s   = blockIdx.y;
    const int tid = threadIdx.x;

    __shared__ float s_coef[QPER];
    __shared__ float s_MZ[2];

    if (tid < 32) {
        const float* mb = g_m + b * NCHUNK;
        const float* sb = g_s + b * NCHUNK;

        float m = fmaxf(fmaxf(mb[tid], mb[tid + 32]),
                        fmaxf(mb[tid + 64], mb[tid + 96]));
        #pragma unroll
        for (int o = 16; o > 0; o >>= 1)
            m = fmaxf(m, __shfl_xor_sync(0xffffffffu, m, o));
        // all lanes now hold M

        float z = sb[tid]      * __expf(mb[tid]      - m)
                + sb[tid + 32] * __expf(mb[tid + 32] - m)
                + sb[tid + 64] * __expf(mb[tid + 64] - m)
                + sb[tid + 96] * __expf(mb[tid + 96] - m);
        #pragma unroll
        for (int o = 16; o > 0; o >>= 1)
            z += __shfl_xor_sync(0xffffffffu, z, o);

        if (tid == 0) { s_MZ[0] = m; s_MZ[1] = 1.0f / z; }
    }
    __syncthreads();
    const float M    = s_MZ[0];
    const float invZ = s_MZ[1];

    if (tid < QPER)
        s_coef[tid] = __expf(g_m[b * NCHUNK + s * QPER + tid] - M) * invZ;
    __syncthreads();

    float acc = 0.f;
    const float* base = g_part + ((size_t)b * NCHUNK + s * QPER) * C_;
    #pragma unroll
    for (int qq = 0; qq < QPER; ++qq)
        acc = fmaf(__ldcs(base + qq * C_ + tid), s_coef[qq], acc);  // coalesced
    g_part2[(b * QSPLIT + s) * C_ + tid] = acc;
}

// ---------------------------------------------------------------------------
// K3b: fold split partials -> output. grid = B_, block = 256.
// ---------------------------------------------------------------------------
__global__ __launch_bounds__(256) void combine_fold_kernel(float* __restrict__ out)
{
    const int b   = blockIdx.x;
    const int tid = threadIdx.x;

    float acc = 0.f;
    #pragma unroll
    for (int s = 0; s < QSPLIT; ++s)
        acc += g_part2[(b * QSPLIT + s) * C_ + tid];   // coalesced, MLP=8
    out[b * C_ + tid] = acc;
}

// ---------------------------------------------------------------------------
// Launch. Input order (metadata): h_dec, fm, W_fm, b_fm(unused), W_h, b_h
// ---------------------------------------------------------------------------
extern "C" void kernel_launch(void* const* d_in, const int* in_sizes, int n_in,
                              void* d_out, int out_size)
{
    const float* h_dec = (const float*)d_in[0];
    const float* fm    = (const float*)d_in[1];
    const float* W_fm  = (const float*)d_in[2];
    // d_in[3] = b_fm — cancels in softmax, unused
    const float* W_h   = (const float*)d_in[4];
    const float* b_h   = (const float*)d_in[5];
    float* out = (float*)d_out;

    prep_a_kernel<<<dim3(B_, KSPLIT), 256>>>(h_dec, W_h);
    prep_b_kernel<<<B_, 256>>>(b_h, W_fm);
    pass_kernel<<<dim3(NCHUNK, B_), 256>>>(fm);
    combine_split_kernel<<<dim3(B_, QSPLIT), 256>>>();
    combine_fold_kernel<<<B_, 256>>>(out);
}

// round 8
// speedup vs baseline: 3.1533x; 1.0662x over previous
#include <cuda_runtime.h>
#include <math_constants.h>
#include <cstdint>

// Problem constants
#define B_     32
#define HS_    512
#define C_     256
#define HW_    4096
#define A_     256
#define CHUNK  32                 // pixels per sub-tile in the pass
#define PITER  4                  // sub-tiles per block (online softmax)
#define BLKPIX (CHUNK * PITER)    // 128 pixels per block
#define NCHUNK (HW_ / BLKPIX)     // 32 blocks per batch
#define KSPLIT 8                  // split-K factor for wh
#define QSPLIT 8                  // split factor for the combine reduction
#define QPER   (NCHUNK / QSPLIT)  // 4 chunks per combine block

// Scratch (allocation-free rule: __device__ globals)
__device__ float g_whp[B_ * KSPLIT * A_];    // split-K partials of wh
__device__ float g_v[B_ * C_];               // v[b,c] = W_fm @ wh[b]
__device__ float g_m[B_ * NCHUNK];           // per-chunk running max
__device__ float g_s[B_ * NCHUNK];           // per-chunk exp-sum
__device__ float g_part[B_ * NCHUNK * C_];   // per-chunk partial context (1 MB)
__device__ float g_part2[B_ * QSPLIT * C_];  // combine split partials (256 KB)

// ---------------------------------------------------------------------------
// K1a: split-K partial of wh[b] = h_dec[b] @ W_h.
// grid = (B_, KSPLIT) = 256 blocks, block = 256.
// ---------------------------------------------------------------------------
__global__ __launch_bounds__(256) void prep_a_kernel(
    const float* __restrict__ h_dec,  // (B, HS)
    const float* __restrict__ W_h)    // (HS, A)
{
    const int b   = blockIdx.x;
    const int s   = blockIdx.y;
    const int tid = threadIdx.x;
    const int hs0 = s * (HS_ / KSPLIT);     // 64 rows per split

    __shared__ float sh[HS_ / KSPLIT];
    if (tid < HS_ / KSPLIT)
        sh[tid] = h_dec[b * HS_ + hs0 + tid];
    __syncthreads();

    float acc = 0.f;
    #pragma unroll 8
    for (int hs = 0; hs < HS_ / KSPLIT; ++hs)
        acc = fmaf(sh[hs], W_h[(size_t)(hs0 + hs) * A_ + tid], acc);  // coalesced
    g_whp[(b * KSPLIT + s) * A_ + tid] = acc;
}

// ---------------------------------------------------------------------------
// K1b: fold split-K partials + b_h -> wh; then v[b,c] = W_fm[c,:]·wh.
// grid = (B_, 2) = 64 blocks; 2 threads per channel, each half of A.
// ---------------------------------------------------------------------------
__global__ __launch_bounds__(256) void prep_b_kernel(
    const float* __restrict__ b_h,    // (A)
    const float* __restrict__ W_fm)   // (C, A)
{
    const int b   = blockIdx.x;
    const int cy  = blockIdx.y;       // channel half: 0 or 1
    const int tid = threadIdx.x;

    __shared__ float wh[A_];
    __shared__ float s2[256];

    float acc = b_h[tid];
    #pragma unroll
    for (int s = 0; s < KSPLIT; ++s)
        acc += g_whp[(b * KSPLIT + s) * A_ + tid];   // coalesced
    wh[tid] = acc;
    __syncthreads();

    const int c_local = tid >> 1;              // 0..127
    const int half    = tid & 1;               // A half
    const int c       = cy * 128 + c_local;
    const int a0      = half * (A_ / 2);       // 128

    const float4* wrow = (const float4*)(W_fm + (size_t)c * A_ + a0);
    float vv = 0.f;
    #pragma unroll 8
    for (int a4 = 0; a4 < A_ / 8; ++a4) {      // 32 float4
        float4 w4 = wrow[a4];
        vv = fmaf(w4.x, wh[a0 + a4 * 4 + 0],
             fmaf(w4.y, wh[a0 + a4 * 4 + 1],
             fmaf(w4.z, wh[a0 + a4 * 4 + 2],
             fmaf(w4.w, wh[a0 + a4 * 4 + 3], vv))));
    }
    s2[tid] = vv;
    __syncthreads();

    if (tid < 128)
        g_v[b * C_ + cy * 128 + tid] = s2[2 * tid] + s2[2 * tid + 1];
}

// ---------------------------------------------------------------------------
// K2: main single-DRAM-pass kernel with online softmax over PITER sub-tiles.
// grid = (NCHUNK, B) = 1024 blocks, block = 256.
// Per iteration: prefetch next sub-tile's 8 float4 BEFORE the barriers, so
// loads stay in flight through the score/softmax phase.
// ---------------------------------------------------------------------------
__global__ __launch_bounds__(256) void pass_kernel(const float* __restrict__ fm)
{
    __shared__ float s_v[C_];
    __shared__ float s_red[CHUNK * 33];   // [pixel][group] padded
    __shared__ float s_part[C_ * 9];      // [channel][quad] padded
    __shared__ float s_w[CHUNK];
    __shared__ float s_scale;

    const int b     = blockIdx.y;
    const int q     = blockIdx.x;
    const int p0    = q * BLKPIX;
    const int tid   = threadIdx.x;
    const int j     = tid & 7;            // quad (4 pixels)
    const int g     = tid >> 3;           // channel group 0..31
    const int pbase = j * 4;

    s_v[tid] = g_v[b * C_ + tid];

    const float* fmb = fm + (size_t)b * C_ * HW_ + p0 + j * 4;

    // prefetch sub-tile 0
    float4 val[8], valn[8];
    #pragma unroll
    for (int k = 0; k < 8; ++k)
        val[k] = __ldcs((const float4*)(fmb + (size_t)(g + 32 * k) * HW_));

    __syncthreads();   // s_v ready

    float ctx[8];
    #pragma unroll
    for (int k = 0; k < 8; ++k) ctx[k] = 0.f;
    float m_run = -CUDART_INF_F;   // live in warp 0 lanes
    float s_run = 0.f;

    #pragma unroll
    for (int it = 0; it < PITER; ++it) {
        // prefetch next sub-tile (issues before barriers below)
        if (it + 1 < PITER) {
            #pragma unroll
            for (int k = 0; k < 8; ++k)
                valn[k] = __ldcs((const float4*)(fmb + (size_t)(g + 32 * k) * HW_
                                                 + (it + 1) * CHUNK));
        }

        // score partials for my 4 pixels over my 8 channels
        float sc0 = 0.f, sc1 = 0.f, sc2 = 0.f, sc3 = 0.f;
        #pragma unroll
        for (int k = 0; k < 8; ++k) {
            const float vr = s_v[g + 32 * k];
            sc0 = fmaf(val[k].x, vr, sc0);
            sc1 = fmaf(val[k].y, vr, sc1);
            sc2 = fmaf(val[k].z, vr, sc2);
            sc3 = fmaf(val[k].w, vr, sc3);
        }
        s_red[(pbase + 0) * 33 + g] = sc0;
        s_red[(pbase + 1) * 33 + g] = sc1;
        s_red[(pbase + 2) * 33 + g] = sc2;
        s_red[(pbase + 3) * 33 + g] = sc3;
        __syncthreads();

        // warp 0: fold, running max/sum, weights
        if (tid < 32) {
            float sc = 0.f;
            #pragma unroll
            for (int gg = 0; gg < 32; ++gg)
                sc += s_red[tid * 33 + gg];

            float m_i = sc;
            #pragma unroll
            for (int o = 16; o > 0; o >>= 1)
                m_i = fmaxf(m_i, __shfl_xor_sync(0xffffffffu, m_i, o));

            const float m_new     = fmaxf(m_run, m_i);
            const float scale_old = __expf(m_run - m_new);   // 0 on first iter

            const float w = __expf(sc - m_new);
            s_w[tid] = w;

            float ssum = w;
            #pragma unroll
            for (int o = 16; o > 0; o >>= 1)
                ssum += __shfl_xor_sync(0xffffffffu, ssum, o);

            s_run = s_run * scale_old + ssum;
            m_run = m_new;
            if (tid == 0) s_scale = scale_old;
        }
        __syncthreads();

        // rescale + accumulate context from registers
        const float scl = s_scale;
        const float w0 = s_w[pbase + 0];
        const float w1 = s_w[pbase + 1];
        const float w2 = s_w[pbase + 2];
        const float w3 = s_w[pbase + 3];
        #pragma unroll
        for (int k = 0; k < 8; ++k) {
            float a = fmaf(val[k].x, w0,
                      fmaf(val[k].y, w1,
                      fmaf(val[k].z, w2, val[k].w * w3)));
            ctx[k] = fmaf(ctx[k], scl, a);
        }

        // rotate prefetch buffer
        if (it + 1 < PITER) {
            #pragma unroll
            for (int k = 0; k < 8; ++k) val[k] = valn[k];
        }
    }

    if (tid == 0) {
        g_m[b * NCHUNK + q] = m_run;
        g_s[b * NCHUNK + q] = s_run;
    }

    // fold quads per channel, coalesced store
    #pragma unroll
    for (int k = 0; k < 8; ++k)
        s_part[(g + 32 * k) * 9 + j] = ctx[k];
    __syncthreads();

    float acc = 0.f;
    #pragma unroll
    for (int jj = 0; jj < 8; ++jj)
        acc += s_part[tid * 9 + jj];
    g_part[((size_t)(b * NCHUNK + q)) * C_ + tid] = acc;
}

// ---------------------------------------------------------------------------
// K3a: split combine. grid = (B_, QSPLIT) = 256 blocks, block = 256.
// ---------------------------------------------------------------------------
__global__ __launch_bounds__(256) void combine_split_kernel()
{
    const int b   = blockIdx.x;
    const int s   = blockIdx.y;
    const int tid = threadIdx.x;

    __shared__ float s_coef[QPER];
    __shared__ float s_MZ[2];

    if (tid < 32) {
        const float* mb = g_m + b * NCHUNK;
        const float* sb = g_s + b * NCHUNK;

        float m = mb[tid];
        #pragma unroll
        for (int o = 16; o > 0; o >>= 1)
            m = fmaxf(m, __shfl_xor_sync(0xffffffffu, m, o));

        float z = sb[tid] * __expf(mb[tid] - m);
        #pragma unroll
        for (int o = 16; o > 0; o >>= 1)
            z += __shfl_xor_sync(0xffffffffu, z, o);

        if (tid == 0) { s_MZ[0] = m; s_MZ[1] = 1.0f / z; }
    }
    __syncthreads();
    const float M    = s_MZ[0];
    const float invZ = s_MZ[1];

    if (tid < QPER)
        s_coef[tid] = __expf(g_m[b * NCHUNK + s * QPER + tid] - M) * invZ;
    __syncthreads();

    float acc = 0.f;
    const float* base = g_part + ((size_t)b * NCHUNK + s * QPER) * C_;
    #pragma unroll
    for (int qq = 0; qq < QPER; ++qq)
        acc = fmaf(base[qq * C_ + tid], s_coef[qq], acc);  // coalesced
    g_part2[(b * QSPLIT + s) * C_ + tid] = acc;
}

// ---------------------------------------------------------------------------
// K3b: fold split partials -> output. grid = B_, block = 256.
// ---------------------------------------------------------------------------
__global__ __launch_bounds__(256) void combine_fold_kernel(float* __restrict__ out)
{
    const int b   = blockIdx.x;
    const int tid = threadIdx.x;

    float acc = 0.f;
    #pragma unroll
    for (int s = 0; s < QSPLIT; ++s)
        acc += g_part2[(b * QSPLIT + s) * C_ + tid];   // coalesced, MLP=8
    out[b * C_ + tid] = acc;
}

// ---------------------------------------------------------------------------
// Launch. Input order (metadata): h_dec, fm, W_fm, b_fm(unused), W_h, b_h
// ---------------------------------------------------------------------------
extern "C" void kernel_launch(void* const* d_in, const int* in_sizes, int n_in,
                              void* d_out, int out_size)
{
    const float* h_dec = (const float*)d_in[0];
    const float* fm    = (const float*)d_in[1];
    const float* W_fm  = (const float*)d_in[2];
    // d_in[3] = b_fm — cancels in softmax, unused
    const float* W_h   = (const float*)d_in[4];
    const float* b_h   = (const float*)d_in[5];
    float* out = (float*)d_out;

    prep_a_kernel<<<dim3(B_, KSPLIT), 256>>>(h_dec, W_h);
    prep_b_kernel<<<dim3(B_, 2), 256>>>(b_h, W_fm);
    pass_kernel<<<dim3(NCHUNK, B_), 256>>>(fm);
    combine_split_kernel<<<dim3(B_, QSPLIT), 256>>>();
    combine_fold_kernel<<<B_, 256>>>(out);
}